// round 5
// baseline (speedup 1.0000x reference)
#include <cuda_runtime.h>

#define BB 2
#define CC 512
#define NSd 2048
#define NGd 2000
#define NV 300

// ---- output layout (floats), concatenated reference tuple ----
static constexpr size_t O_VS    = 0;                                   // (B,NS,300)
static constexpr size_t O_VPROT = O_VS    + (size_t)BB*NSd*NV;         // (B,NS,3,3)
static constexpr size_t O_SC    = O_VPROT + (size_t)BB*NSd*9;          // (B,NS,12,4)
static constexpr size_t O_WD    = O_SC    + (size_t)BB*NSd*48;         // (B,NS,12,4)
static constexpr size_t O_TROT  = O_WD    + (size_t)BB*NSd*48;         // (B,NS,3,3)
static constexpr size_t O_TSC   = O_TROT  + (size_t)BB*NSd*9;          // (B,NS,12,4)
static constexpr size_t O_TWD   = O_TSC   + (size_t)BB*NSd*48;         // (B,NS,12,4)
static constexpr size_t O_GN    = O_TWD   + (size_t)BB*NSd*48;         // (B,NS,300)
static constexpr size_t O_GP    = O_GN    + (size_t)BB*NSd*NV;         // (B,NS,3)

// ---- device scratch (no allocations allowed) ----
__device__ float g_views[NV*3];
__device__ float g_views_rot[NV*9];
__device__ float g_R[BB*9];
__device__ float g_t[BB*3];
__device__ int   g_view_inds[BB*NV];
__device__ float g_gvrot[BB*NV*9];     // R @ views_rot[view_inds[v]]
__device__ float g_gpt[BB*NGd*3];      // transformed grasp points
__device__ int   g_nn[BB*NSd];
__device__ int   g_topv[BB*NSd];
__device__ float g_tmp[(size_t)BB*CC*NSd];
__device__ float g_res[(size_t)BB*CC*NSd];
__device__ unsigned g_umax, g_umin;

// ---------------------------------------------------------------
__device__ __forceinline__ void make_rot(float tx_, float ty_, float tz_, float* m)
{
    float ax0 = tx_, ax1 = ty_, ax2 = tz_;
    float ay0 = -ax1, ay1 = ax0, ay2 = 0.f;
    float yn = sqrtf(ay0*ay0 + ay1*ay1 + ay2*ay2);
    if (yn == 0.f) { ay0 = 0.f; ay1 = 1.f; ay2 = 0.f; }
    float an = sqrtf(ax0*ax0 + ax1*ax1 + ax2*ax2);
    ax0 /= an; ax1 /= an; ax2 /= an;
    float an2 = sqrtf(ay0*ay0 + ay1*ay1 + ay2*ay2);
    ay0 /= an2; ay1 /= an2; ay2 /= an2;
    float az0 = ax1*ay2 - ax2*ay1;
    float az1 = ax2*ay0 - ax0*ay2;
    float az2 = ax0*ay1 - ax1*ay0;
    m[0]=ax0; m[1]=ay0; m[2]=az0;
    m[3]=ax1; m[4]=ay1; m[5]=az1;
    m[6]=ax2; m[7]=ay2; m[8]=az2;
}

__global__ void k_views()
{
    int v = threadIdx.x;
    if (v >= NV) return;
    float fv = (float)v;
    float Z = (2.f*fv + 1.f) / 300.f - 1.f;
    float r = sqrtf(fmaxf(1.f - Z*Z, 0.f));
    float ang = (6.2831853071795864769f * fv) * 0.61803398874989484820f;
    float X = r * cosf(ang);
    float Y = r * sinf(ang);
    g_views[v*3+0] = X; g_views[v*3+1] = Y; g_views[v*3+2] = Z;
    make_rot(-X, -Y, -Z, &g_views_rot[v*9]);
}

__global__ void k_batch(const float* __restrict__ pose)
{
    __shared__ float sR[9];
    __shared__ float sgx[NV], sgy[NV], sgz[NV], srr[NV];
    int b = blockIdx.x, tid = threadIdx.x;
    if (tid < 9) {
        float val = pose[b*12 + (tid/3)*4 + (tid%3)];
        sR[tid] = val; g_R[b*9+tid] = val;
    }
    if (tid < 3) g_t[b*3+tid] = pose[b*12 + tid*4 + 3];
    __syncthreads();
    if (tid < NV) {
        float vx = g_views[tid*3], vy = g_views[tid*3+1], vz = g_views[tid*3+2];
        float gx = sR[0]*vx + sR[1]*vy + sR[2]*vz;
        float gy = sR[3]*vx + sR[4]*vy + sR[5]*vz;
        float gz = sR[6]*vx + sR[7]*vy + sR[8]*vz;
        sgx[tid]=gx; sgy[tid]=gy; sgz[tid]=gz;
        srr[tid]=gx*gx + gy*gy + gz*gz;
    }
    __syncthreads();
    if (tid < NV) {
        float qx = g_views[tid*3], qy = g_views[tid*3+1], qz = g_views[tid*3+2];
        float qq = qx*qx + qy*qy + qz*qz;
        float best = 1e30f; int bi = 0;
        for (int u = 0; u < NV; u++) {
            float d = (qq + srr[u]) - 2.f*(qx*sgx[u] + qy*sgy[u] + qz*sgz[u]);
            if (d < best) { best = d; bi = u; }
        }
        g_view_inds[b*NV + tid] = bi;
        const float* VR = g_views_rot + bi*9;
        float* O = g_gvrot + (size_t)(b*NV + tid)*9;
#pragma unroll
        for (int i = 0; i < 3; i++)
#pragma unroll
            for (int j = 0; j < 3; j++)
                O[i*3+j] = sR[i*3+0]*VR[0+j] + sR[i*3+1]*VR[3+j] + sR[i*3+2]*VR[6+j];
    }
}

__global__ void k_gptrans(const float* __restrict__ gp)
{
    int idx = blockIdx.x*blockDim.x + threadIdx.x;
    if (idx >= BB*NGd) return;
    int b = idx / NGd;
    float p0 = gp[idx*3+0], p1 = gp[idx*3+1], p2 = gp[idx*3+2];
    const float* R = g_R + b*9;
    const float* t = g_t + b*3;
    g_gpt[idx*3+0] = R[0]*p0 + R[1]*p1 + R[2]*p2 + t[0];
    g_gpt[idx*3+1] = R[3]*p0 + R[4]*p1 + R[5]*p2 + t[1];
    g_gpt[idx*3+2] = R[6]*p0 + R[7]*p1 + R[8]*p2 + t[2];
}

// ---------------- GEMM: Y = act(W @ X + b), K=512, N=2048 ----------------
__device__ __forceinline__ void gemm_body(
    const float* __restrict__ W, const float* __restrict__ X,
    const float* __restrict__ bias, float* __restrict__ Y,
    int M, int mode, int do_relu)
{
    constexpr int N = NSd, K = CC;
    __shared__ float As[16][68];
    __shared__ float Bs[16][64];
    const int b   = blockIdx.z;
    const int bm0 = blockIdx.y * 64;
    const int bn0 = blockIdx.x * 64;
    const float* Xb = X + (size_t)b * K * N;
    const int tid = threadIdx.x;
    const int tx = tid & 15, ty = tid >> 4;
    float acc[4][4];
#pragma unroll
    for (int i = 0; i < 4; i++)
#pragma unroll
        for (int j = 0; j < 4; j++) acc[i][j] = 0.f;

    for (int k0 = 0; k0 < K; k0 += 16) {
#pragma unroll
        for (int j = 0; j < 4; j++) {
            int l = tid + j*256;
            int m = l >> 4, kk = l & 15;
            int gm = bm0 + m;
            As[kk][m] = (gm < M) ? W[(size_t)gm*K + k0 + kk] : 0.f;
        }
#pragma unroll
        for (int j = 0; j < 4; j++) {
            int l = tid + j*256;
            int nn = l & 63, kk = l >> 6;
            Bs[kk][nn] = Xb[(size_t)(k0+kk)*N + bn0 + nn];
        }
        __syncthreads();
#pragma unroll
        for (int kk = 0; kk < 16; kk++) {
            float4 av = *(const float4*)&As[kk][ty*4];
            float4 bv = *(const float4*)&Bs[kk][tx*4];
            float am[4] = {av.x, av.y, av.z, av.w};
            float bn[4] = {bv.x, bv.y, bv.z, bv.w};
#pragma unroll
            for (int i = 0; i < 4; i++)
#pragma unroll
                for (int j = 0; j < 4; j++)
                    acc[i][j] = fmaf(am[i], bn[j], acc[i][j]);
        }
        __syncthreads();
    }
#pragma unroll
    for (int i = 0; i < 4; i++) {
        int m = bm0 + ty*4 + i;
        if (m >= M) continue;
        float bv = bias[m];
        if (mode == 0) {
            float4 o;
            float* p = &Y[((size_t)b*M + m)*N + bn0 + tx*4];
            o.x = acc[i][0] + bv; o.y = acc[i][1] + bv;
            o.z = acc[i][2] + bv; o.w = acc[i][3] + bv;
            if (do_relu) {
                o.x = fmaxf(o.x, 0.f); o.y = fmaxf(o.y, 0.f);
                o.z = fmaxf(o.z, 0.f); o.w = fmaxf(o.w, 0.f);
            }
            *(float4*)p = o;
        } else {
#pragma unroll
            for (int j = 0; j < 4; j++) {
                int n = bn0 + tx*4 + j;
                float v = acc[i][j] + bv;
                if (do_relu) v = fmaxf(v, 0.f);
                if (mode == 1) {
                    Y[((size_t)b*N + n)*NV + m] = v;   // view_scores (B,NS,300)
                } else {                               // sw2 scatter: score / width
                    size_t base = (m < 48)
                        ? ((size_t)b*NSd + n)*48 + m
                        : (size_t)BB*NSd*48 + ((size_t)b*NSd + n)*48 + (m - 48);
                    Y[base] = v;
                }
            }
        }
    }
}

__global__ __launch_bounds__(256) void k_gemm1(const float* W, const float* bias, const float* X)
{ gemm_body(W, X, bias, g_tmp, 512, 0, 1); }
__global__ __launch_bounds__(256) void k_gemm2(const float* W, const float* bias)
{ gemm_body(W, g_tmp, bias, g_res, 512, 0, 1); }
__global__ __launch_bounds__(256) void k_gemm3(const float* W, const float* bias, float* out)
{ gemm_body(W, g_res, bias, out + O_VS, 300, 1, 0); }
__global__ __launch_bounds__(256) void k_gemm4(const float* W, const float* bias)
{ gemm_body(W, g_res, bias, g_tmp, 512, 0, 1); }
__global__ __launch_bounds__(256) void k_gemm5(const float* W, const float* bias, float* out)
{ gemm_body(W, g_tmp, bias, out + O_SC, 96, 2, 0); }

// ---------------- argmax over views + vp_rot ----------------
__global__ void k_argmax(float* __restrict__ out)
{
    int g = (blockIdx.x * blockDim.x + threadIdx.x) >> 5;
    int lane = threadIdx.x & 31;
    if (g >= BB*NSd) return;
    const float* vs = out + O_VS + (size_t)g * NV;
    float best = -1e30f; int bi = 1 << 30;
    for (int v = lane; v < NV; v += 32) {
        float val = vs[v];
        if (val > best) { best = val; bi = v; }
    }
#pragma unroll
    for (int off = 16; off; off >>= 1) {
        float ob = __shfl_xor_sync(0xffffffffu, best, off);
        int   oi = __shfl_xor_sync(0xffffffffu, bi,  off);
        if (ob > best || (ob == best && oi < bi)) { best = ob; bi = oi; }
    }
    if (lane == 0) {
        g_topv[g] = bi;
        float m[9];
        make_rot(-g_views[bi*3], -g_views[bi*3+1], -g_views[bi*3+2], m);
        float* o = out + O_VPROT + (size_t)g*9;
#pragma unroll
        for (int i = 0; i < 9; i++) o[i] = m[i];
    }
}

// ---------------- kNN seeds -> grasp points, gp gather ----------------
__global__ void k_nn(const float* __restrict__ pc, float* __restrict__ out)
{
    __shared__ float sx[256], sy[256], sz[256], sr[256];
    int b = blockIdx.y;
    int n = blockIdx.x*256 + threadIdx.x;
    float qx = pc[((size_t)b*NSd + n)*3 + 0];
    float qy = pc[((size_t)b*NSd + n)*3 + 1];
    float qz = pc[((size_t)b*NSd + n)*3 + 2];
    float qq = qx*qx + qy*qy + qz*qz;
    float best = 1e30f; int bi = 0;
    for (int t0 = 0; t0 < NGd; t0 += 256) {
        int r = t0 + threadIdx.x;
        if (r < NGd) {
            float x = g_gpt[((size_t)b*NGd + r)*3 + 0];
            float y = g_gpt[((size_t)b*NGd + r)*3 + 1];
            float z = g_gpt[((size_t)b*NGd + r)*3 + 2];
            sx[threadIdx.x] = x; sy[threadIdx.x] = y; sz[threadIdx.x] = z;
            sr[threadIdx.x] = x*x + y*y + z*z;
        } else { sx[threadIdx.x] = 0.f; sy[threadIdx.x] = 0.f; sz[threadIdx.x] = 0.f; sr[threadIdx.x] = 1e30f; }
        __syncthreads();
        int cnt = min(256, NGd - t0);
        for (int j = 0; j < cnt; j++) {
            float d = (qq + sr[j]) - 2.f*(qx*sx[j] + qy*sy[j] + qz*sz[j]);
            if (d < best) { best = d; bi = t0 + j; }
        }
        __syncthreads();
    }
    g_nn[b*NSd + n] = bi;
    out[O_GP + ((size_t)b*NSd + n)*3 + 0] = g_gpt[((size_t)b*NGd + bi)*3 + 0];
    out[O_GP + ((size_t)b*NSd + n)*3 + 1] = g_gpt[((size_t)b*NGd + bi)*3 + 1];
    out[O_GP + ((size_t)b*NSd + n)*3 + 2] = g_gpt[((size_t)b*NGd + bi)*3 + 2];
}

__global__ void k_init_reduce()
{
    g_umax = 0u;           // bits of 0.0f
    g_umin = 0x7f800000u;  // bits of +inf
}

// ---------------- graspness + top-view gather ----------------
__global__ __launch_bounds__(256) void k_grasp(
    const float* __restrict__ gl, const float* __restrict__ gw, float* __restrict__ out)
{
    __shared__ float s_cnt[NV];
    __shared__ int   s_vi[NV];
    __shared__ float s_perm[NV];
    __shared__ float s_red[16];
    __shared__ float s_top[48];
    __shared__ float s_mx, s_mn;

    int idx = blockIdx.x;              // b*NSd + n
    int b = idx / NSd;
    int tid = threadIdx.x;
    int lane = tid & 31, w = tid >> 5;

    int nn = g_nn[idx];
    int tv = g_topv[idx];
    for (int v = tid; v < NV; v += 256) s_vi[v] = g_view_inds[b*NV + v];

    const float* row = gl + (size_t)(b*NGd + nn) * (NV*48);
    for (int u = w; u < NV; u += 8) {
        const float* p = row + u*48;
        float v1 = __ldg(p + lane);
        bool m1 = (v1 > 0.f) & (v1 <= 0.6f);
        bool m2 = false;
        if (lane < 16) { float v2 = __ldg(p + 32 + lane); m2 = (v2 > 0.f) & (v2 <= 0.6f); }
        unsigned b1 = __ballot_sync(0xffffffffu, m1);
        unsigned b2 = __ballot_sync(0xffffffffu, m2);
        if (lane == 0) s_cnt[u] = (float)(__popc(b1) + __popc(b2));
    }
    __syncthreads();

    float lmx = -1e30f, lmn = 1e30f;
    for (int v = tid; v < NV; v += 256) {
        float gv = s_cnt[s_vi[v]] * (1.f/48.f);
        s_perm[v] = gv;
        lmx = fmaxf(lmx, gv); lmn = fminf(lmn, gv);
    }
#pragma unroll
    for (int off = 16; off; off >>= 1) {
        lmx = fmaxf(lmx, __shfl_xor_sync(0xffffffffu, lmx, off));
        lmn = fminf(lmn, __shfl_xor_sync(0xffffffffu, lmn, off));
    }
    if (lane == 0) { s_red[w] = lmx; s_red[8+w] = lmn; }
    __syncthreads();
    if (tid == 0) {
        float mx = -1e30f, mn = 1e30f;
        for (int i = 0; i < 8; i++) { mx = fmaxf(mx, s_red[i]); mn = fminf(mn, s_red[8+i]); }
        s_mx = mx; s_mn = mn;
    }
    __syncthreads();
    {
        float mn = s_mn, den = s_mx - s_mn + 1e-8f;
        for (int v = tid; v < NV; v += 256)
            out[O_GN + (size_t)idx*NV + v] = (s_perm[v] - mn) / den;
    }

    // top-view slice
    int ut = s_vi[tv];
    if (tid < 48) {
        float sc = __ldg(row + ut*48 + tid);
        float wd = __ldg(gw + (size_t)(b*NGd + nn)*(NV*48) + ut*48 + tid);
        bool lm = (sc > 0.f) & (wd <= 0.1f);
        float scv = lm ? sc : 0.f;
        out[O_TSC + (size_t)idx*48 + tid] = scv;
        out[O_TWD + (size_t)idx*48 + tid] = wd;
        s_top[tid] = scv;
    }
    if (tid >= 64 && tid < 73)
        out[O_TROT + (size_t)idx*9 + (tid - 64)] = g_gvrot[(size_t)(b*NV + tv)*9 + (tid - 64)];
    __syncthreads();
    if (tid == 0) {
        float mx = 0.f, mnp = 1e30f; bool any = false;
        for (int i = 0; i < 48; i++) {
            float v = s_top[i];
            mx = fmaxf(mx, v);
            if (v > 0.f) { any = true; mnp = fminf(mnp, v); }
        }
        atomicMax(&g_umax, __float_as_uint(mx));
        if (any) atomicMin(&g_umin, __float_as_uint(mnp));
    }
}

__global__ void k_finalize(float* __restrict__ out)
{
    int i = blockIdx.x*blockDim.x + threadIdx.x;
    if (i >= BB*NSd*48) return;
    float v = out[O_TSC + i];
    if (v > 0.f) {
        float umax = __uint_as_float(g_umax);
        float umin = __uint_as_float(g_umin);
        out[O_TSC + i] = logf(umax / v) / (logf(umax / umin) + 1e-8f);
    }
}

// ---------------------------------------------------------------
extern "C" void kernel_launch(void* const* d_in, const int* in_sizes, int n_in,
                              void* d_out, int out_size)
{
    const float* seed  = (const float*)d_in[0];
    const float* pc    = (const float*)d_in[1];
    const float* pose  = (const float*)d_in[2];
    const float* gpts  = (const float*)d_in[3];
    const float* gl    = (const float*)d_in[4];
    const float* gw    = (const float*)d_in[5];
    const float* aw1w  = (const float*)d_in[6];
    const float* aw1b  = (const float*)d_in[7];
    const float* aw2w  = (const float*)d_in[8];
    const float* aw2b  = (const float*)d_in[9];
    const float* aw3w  = (const float*)d_in[10];
    const float* aw3b  = (const float*)d_in[11];
    const float* sw1w  = (const float*)d_in[12];
    const float* sw1b  = (const float*)d_in[13];
    const float* sw2w  = (const float*)d_in[14];
    const float* sw2b  = (const float*)d_in[15];
    float* out = (float*)d_out;

    k_views<<<1, 320>>>();
    k_batch<<<BB, 320>>>(pose);
    k_gptrans<<<(BB*NGd + 255)/256, 256>>>(gpts);

    k_gemm1<<<dim3(32, 8, BB), 256>>>(aw1w, aw1b, seed);
    k_gemm2<<<dim3(32, 8, BB), 256>>>(aw2w, aw2b);
    k_gemm3<<<dim3(32, 5, BB), 256>>>(aw3w, aw3b, out);
    k_gemm4<<<dim3(32, 8, BB), 256>>>(sw1w, sw1b);
    k_gemm5<<<dim3(32, 2, BB), 256>>>(sw2w, sw2b, out);

    k_argmax<<<(BB*NSd*32)/256, 256>>>(out);
    k_nn<<<dim3(NSd/256, BB), 256>>>(pc, out);
    k_init_reduce<<<1, 1>>>();
    k_grasp<<<BB*NSd, 256>>>(gl, gw, out);
    k_finalize<<<(BB*NSd*48 + 255)/256, 256>>>(out);
}

// round 7
// speedup vs baseline: 1.0696x; 1.0696x over previous
#include <cuda_runtime.h>

#define BB 2
#define CC 512
#define NSd 2048
#define NGd 2000
#define NV 300

// ---- output layout (floats), concatenated reference tuple ----
static constexpr size_t O_VS    = 0;                                   // (B,NS,300)
static constexpr size_t O_VPROT = O_VS    + (size_t)BB*NSd*NV;         // (B,NS,3,3)
static constexpr size_t O_SC    = O_VPROT + (size_t)BB*NSd*9;          // (B,NS,12,4)
static constexpr size_t O_WD    = O_SC    + (size_t)BB*NSd*48;         // (B,NS,12,4)
static constexpr size_t O_TROT  = O_WD    + (size_t)BB*NSd*48;         // (B,NS,3,3)
static constexpr size_t O_TSC   = O_TROT  + (size_t)BB*NSd*9;          // (B,NS,12,4)
static constexpr size_t O_TWD   = O_TSC   + (size_t)BB*NSd*48;         // (B,NS,12,4)
static constexpr size_t O_GN    = O_TWD   + (size_t)BB*NSd*48;         // (B,NS,300)
static constexpr size_t O_GP    = O_GN    + (size_t)BB*NSd*NV;         // (B,NS,3)

// ---- device scratch (no allocations allowed) ----
__device__ float g_views[NV*3];
__device__ float g_views_rot[NV*9];
__device__ float g_R[BB*9];
__device__ float g_t[BB*3];
__device__ int   g_view_inds[BB*NV];
__device__ float g_gvrot[BB*NV*9];
__device__ float g_gpt[BB*NGd*3];
__device__ int   g_nn[BB*NSd];
__device__ int   g_topv[BB*NSd];
__device__ float g_tmp[(size_t)BB*CC*NSd];
__device__ float g_res[(size_t)BB*CC*NSd];
__device__ unsigned g_umax, g_umin;

// ---------------------------------------------------------------
__device__ __forceinline__ void make_rot(float tx_, float ty_, float tz_, float* m)
{
    float ax0 = tx_, ax1 = ty_, ax2 = tz_;
    float ay0 = -ax1, ay1 = ax0, ay2 = 0.f;
    float yn = sqrtf(ay0*ay0 + ay1*ay1 + ay2*ay2);
    if (yn == 0.f) { ay0 = 0.f; ay1 = 1.f; ay2 = 0.f; }
    float an = sqrtf(ax0*ax0 + ax1*ax1 + ax2*ax2);
    ax0 /= an; ax1 /= an; ax2 /= an;
    float an2 = sqrtf(ay0*ay0 + ay1*ay1 + ay2*ay2);
    ay0 /= an2; ay1 /= an2; ay2 /= an2;
    float az0 = ax1*ay2 - ax2*ay1;
    float az1 = ax2*ay0 - ax0*ay2;
    float az2 = ax0*ay1 - ax1*ay0;
    m[0]=ax0; m[1]=ay0; m[2]=az0;
    m[3]=ax1; m[4]=ay1; m[5]=az1;
    m[6]=ax2; m[7]=ay2; m[8]=az2;
}

__global__ void k_views()
{
    int v = threadIdx.x;
    if (v >= NV) return;
    float fv = (float)v;
    float Z = (2.f*fv + 1.f) / 300.f - 1.f;
    float r = sqrtf(fmaxf(1.f - Z*Z, 0.f));
    float ang = (6.2831853071795864769f * fv) * 0.61803398874989484820f;
    float X = r * cosf(ang);
    float Y = r * sinf(ang);
    g_views[v*3+0] = X; g_views[v*3+1] = Y; g_views[v*3+2] = Z;
    make_rot(-X, -Y, -Z, &g_views_rot[v*9]);
}

__global__ void k_batch(const float* __restrict__ pose)
{
    __shared__ float sR[9];
    __shared__ float sgx[NV], sgy[NV], sgz[NV], srr[NV];
    int b = blockIdx.x, tid = threadIdx.x;
    if (tid < 9) {
        float val = pose[b*12 + (tid/3)*4 + (tid%3)];
        sR[tid] = val; g_R[b*9+tid] = val;
    }
    if (tid < 3) g_t[b*3+tid] = pose[b*12 + tid*4 + 3];
    __syncthreads();
    if (tid < NV) {
        float vx = g_views[tid*3], vy = g_views[tid*3+1], vz = g_views[tid*3+2];
        float gx = sR[0]*vx + sR[1]*vy + sR[2]*vz;
        float gy = sR[3]*vx + sR[4]*vy + sR[5]*vz;
        float gz = sR[6]*vx + sR[7]*vy + sR[8]*vz;
        sgx[tid]=gx; sgy[tid]=gy; sgz[tid]=gz;
        srr[tid]=gx*gx + gy*gy + gz*gz;
    }
    __syncthreads();
    if (tid < NV) {
        float qx = g_views[tid*3], qy = g_views[tid*3+1], qz = g_views[tid*3+2];
        float qq = qx*qx + qy*qy + qz*qz;
        float best = 1e30f; int bi = 0;
        for (int u = 0; u < NV; u++) {
            float d = (qq + srr[u]) - 2.f*(qx*sgx[u] + qy*sgy[u] + qz*sgz[u]);
            if (d < best) { best = d; bi = u; }
        }
        g_view_inds[b*NV + tid] = bi;
        const float* VR = g_views_rot + bi*9;
        float* O = g_gvrot + (size_t)(b*NV + tid)*9;
#pragma unroll
        for (int i = 0; i < 3; i++)
#pragma unroll
            for (int j = 0; j < 3; j++)
                O[i*3+j] = sR[i*3+0]*VR[0+j] + sR[i*3+1]*VR[3+j] + sR[i*3+2]*VR[6+j];
    }
}

__global__ void k_gptrans(const float* __restrict__ gp)
{
    int idx = blockIdx.x*blockDim.x + threadIdx.x;
    if (idx >= BB*NGd) return;
    int b = idx / NGd;
    float p0 = gp[idx*3+0], p1 = gp[idx*3+1], p2 = gp[idx*3+2];
    const float* R = g_R + b*9;
    const float* t = g_t + b*3;
    g_gpt[idx*3+0] = R[0]*p0 + R[1]*p1 + R[2]*p2 + t[0];
    g_gpt[idx*3+1] = R[3]*p0 + R[4]*p1 + R[5]*p2 + t[1];
    g_gpt[idx*3+2] = R[6]*p0 + R[7]*p1 + R[8]*p2 + t[2];
}

// ---------------- templated SGEMM: Y = act(W @ X + b) ----------------
// BKc = 8 K-chunk, double-buffered smem, (BM/TM)x(BN/TN)=256 threads.
template<int BM,int BN,int TM,int TN,int MODE,int RELU,bool GUARD>
__global__ __launch_bounds__(256) void k_gemm(
    const float* __restrict__ W, const float* __restrict__ X,
    const float* __restrict__ bias, float* __restrict__ Y, int M)
{
    constexpr int K = CC, N = NSd, BKc = 8;
    constexpr int NXt = BN/TN;
    constexpr int AELT = BM*BKc/256;
    constexpr int BELT = BN*BKc/256;
    constexpr int AP = BM + 4;
    __shared__ float As[2][BKc][AP];
    __shared__ float Bs[2][BKc][BN];
    const int b   = blockIdx.z;
    const int bm0 = blockIdx.y * BM;
    const int bn0 = blockIdx.x * BN;
    const float* Xb = X + (size_t)b*K*N + bn0;
    const float* Wb = W + (size_t)bm0*K;
    const int tid = threadIdx.x;
    const int tx = tid % NXt, ty = tid / NXt;

    float acc[TM][TN];
#pragma unroll
    for (int i=0;i<TM;i++)
#pragma unroll
        for (int j=0;j<TN;j++) acc[i][j]=0.f;
    float areg[AELT], breg[BELT];

    // chunk 0
#pragma unroll
    for (int e=0;e<AELT;e++){
        int i = tid + e*256;
        int m = i/BKc, kk = i%BKc;
        float v = 0.f;
        if (!GUARD || (bm0+m) < M) v = Wb[(size_t)m*K + kk];
        As[0][kk][m] = v;
    }
#pragma unroll
    for (int e=0;e<BELT;e++){
        int i = tid + e*256;
        int kk = i/BN, n = i%BN;
        Bs[0][kk][n] = Xb[(size_t)kk*N + n];
    }
    __syncthreads();

    for (int ck=0; ck<K/BKc; ck++){
        const int buf = ck & 1;
        if (ck+1 < K/BKc){
            int k0 = (ck+1)*BKc;
#pragma unroll
            for (int e=0;e<AELT;e++){
                int i = tid + e*256;
                int m = i/BKc, kk = i%BKc;
                float v = 0.f;
                if (!GUARD || (bm0+m) < M) v = Wb[(size_t)m*K + k0 + kk];
                areg[e] = v;
            }
#pragma unroll
            for (int e=0;e<BELT;e++){
                int i = tid + e*256;
                int kk = i/BN, n = i%BN;
                breg[e] = Xb[(size_t)(k0+kk)*N + n];
            }
        }
#pragma unroll
        for (int kk=0;kk<BKc;kk++){
            float af[TM], bf[TN];
#pragma unroll
            for (int i=0;i<TM;i++) af[i] = As[buf][kk][ty*TM+i];
#pragma unroll
            for (int j=0;j<TN;j++) bf[j] = Bs[buf][kk][tx*TN+j];
#pragma unroll
            for (int i=0;i<TM;i++)
#pragma unroll
                for (int j=0;j<TN;j++)
                    acc[i][j] = fmaf(af[i], bf[j], acc[i][j]);
        }
        if (ck+1 < K/BKc){
            const int nb = buf^1;
#pragma unroll
            for (int e=0;e<AELT;e++){ int i = tid + e*256; As[nb][i%BKc][i/BKc] = areg[e]; }
#pragma unroll
            for (int e=0;e<BELT;e++){ int i = tid + e*256; Bs[nb][i/BN][i%BN] = breg[e]; }
        }
        __syncthreads();
    }

#pragma unroll
    for (int i=0;i<TM;i++){
        int m = bm0 + ty*TM + i;
        if (GUARD && m >= M) continue;
        float bv = bias[m];
        if (MODE == 0) {
#pragma unroll
            for (int j0=0;j0<TN;j0+=4){
                float4 o;
                o.x = acc[i][j0+0] + bv; o.y = acc[i][j0+1] + bv;
                o.z = acc[i][j0+2] + bv; o.w = acc[i][j0+3] + bv;
                if (RELU){ o.x=fmaxf(o.x,0.f); o.y=fmaxf(o.y,0.f); o.z=fmaxf(o.z,0.f); o.w=fmaxf(o.w,0.f); }
                *(float4*)&Y[((size_t)b*M + m)*N + bn0 + tx*TN + j0] = o;
            }
        } else {
#pragma unroll
            for (int j=0;j<TN;j++){
                int n = bn0 + tx*TN + j;
                float v = acc[i][j] + bv;
                if (RELU) v = fmaxf(v, 0.f);
                if (MODE == 1) {
                    Y[O_VS + ((size_t)b*N + n)*NV + m] = v;
                } else {
                    size_t base = (m < 48)
                        ? O_SC + ((size_t)b*NSd + n)*48 + m
                        : O_WD + ((size_t)b*NSd + n)*48 + (m - 48);
                    Y[base] = v;
                }
            }
        }
    }
}

// ---------------- argmax over views + vp_rot ----------------
__global__ void k_argmax(float* __restrict__ out)
{
    int g = (blockIdx.x * blockDim.x + threadIdx.x) >> 5;
    int lane = threadIdx.x & 31;
    if (g >= BB*NSd) return;
    const float* vs = out + O_VS + (size_t)g * NV;
    float best = -1e30f; int bi = 1 << 30;
    for (int v = lane; v < NV; v += 32) {
        float val = vs[v];
        if (val > best) { best = val; bi = v; }
    }
#pragma unroll
    for (int off = 16; off; off >>= 1) {
        float ob = __shfl_xor_sync(0xffffffffu, best, off);
        int   oi = __shfl_xor_sync(0xffffffffu, bi,  off);
        if (ob > best || (ob == best && oi < bi)) { best = ob; bi = oi; }
    }
    if (lane == 0) {
        g_topv[g] = bi;
        float m[9];
        make_rot(-g_views[bi*3], -g_views[bi*3+1], -g_views[bi*3+2], m);
        float* o = out + O_VPROT + (size_t)g*9;
#pragma unroll
        for (int i = 0; i < 9; i++) o[i] = m[i];
    }
}

// ---------------- kNN seeds -> grasp points, gp gather ----------------
__global__ void k_nn(const float* __restrict__ pc, float* __restrict__ out)
{
    __shared__ float sx[256], sy[256], sz[256], sr[256];
    int b = blockIdx.y;
    int n = blockIdx.x*256 + threadIdx.x;
    float qx = pc[((size_t)b*NSd + n)*3 + 0];
    float qy = pc[((size_t)b*NSd + n)*3 + 1];
    float qz = pc[((size_t)b*NSd + n)*3 + 2];
    float qq = qx*qx + qy*qy + qz*qz;
    float best = 1e30f; int bi = 0;
    for (int t0 = 0; t0 < NGd; t0 += 256) {
        int r = t0 + threadIdx.x;
        if (r < NGd) {
            float x = g_gpt[((size_t)b*NGd + r)*3 + 0];
            float y = g_gpt[((size_t)b*NGd + r)*3 + 1];
            float z = g_gpt[((size_t)b*NGd + r)*3 + 2];
            sx[threadIdx.x] = x; sy[threadIdx.x] = y; sz[threadIdx.x] = z;
            sr[threadIdx.x] = x*x + y*y + z*z;
        } else { sx[threadIdx.x] = 0.f; sy[threadIdx.x] = 0.f; sz[threadIdx.x] = 0.f; sr[threadIdx.x] = 1e30f; }
        __syncthreads();
        int cnt = min(256, NGd - t0);
        for (int j = 0; j < cnt; j++) {
            float d = (qq + sr[j]) - 2.f*(qx*sx[j] + qy*sy[j] + qz*sz[j]);
            if (d < best) { best = d; bi = t0 + j; }
        }
        __syncthreads();
    }
    g_nn[b*NSd + n] = bi;
    out[O_GP + ((size_t)b*NSd + n)*3 + 0] = g_gpt[((size_t)b*NGd + bi)*3 + 0];
    out[O_GP + ((size_t)b*NSd + n)*3 + 1] = g_gpt[((size_t)b*NGd + bi)*3 + 1];
    out[O_GP + ((size_t)b*NSd + n)*3 + 2] = g_gpt[((size_t)b*NGd + bi)*3 + 2];
}

__global__ void k_init_reduce()
{
    g_umax = 0u;
    g_umin = 0x7f800000u;
}

// ---------------- graspness (heavy scan, overlapped with GEMMs) ----------------
__global__ __launch_bounds__(256) void k_count(
    const float* __restrict__ gl, float* __restrict__ out)
{
    __shared__ float s_cnt[NV];
    __shared__ int   s_vi[NV];
    __shared__ float s_perm[NV];
    __shared__ float s_red[16];
    __shared__ float s_mx, s_mn;

    int idx = blockIdx.x;              // b*NSd + n
    int b = idx / NSd;
    int tid = threadIdx.x;
    int lane = tid & 31, w = tid >> 5;

    int nn = g_nn[idx];
    for (int v = tid; v < NV; v += 256) s_vi[v] = g_view_inds[b*NV + v];

    const float* row = gl + (size_t)(b*NGd + nn) * (NV*48);
    for (int u = w; u < NV; u += 8) {
        const float* p = row + u*48;
        float v1 = __ldg(p + lane);
        bool m1 = (v1 > 0.f) & (v1 <= 0.6f);
        bool m2 = false;
        if (lane < 16) { float v2 = __ldg(p + 32 + lane); m2 = (v2 > 0.f) & (v2 <= 0.6f); }
        unsigned b1 = __ballot_sync(0xffffffffu, m1);
        unsigned b2 = __ballot_sync(0xffffffffu, m2);
        if (lane == 0) s_cnt[u] = (float)(__popc(b1) + __popc(b2));
    }
    __syncthreads();

    float lmx = -1e30f, lmn = 1e30f;
    for (int v = tid; v < NV; v += 256) {
        float gv = s_cnt[s_vi[v]] * (1.f/48.f);
        s_perm[v] = gv;
        lmx = fmaxf(lmx, gv); lmn = fminf(lmn, gv);
    }
#pragma unroll
    for (int off = 16; off; off >>= 1) {
        lmx = fmaxf(lmx, __shfl_xor_sync(0xffffffffu, lmx, off));
        lmn = fminf(lmn, __shfl_xor_sync(0xffffffffu, lmn, off));
    }
    if (lane == 0) { s_red[w] = lmx; s_red[8+w] = lmn; }
    __syncthreads();
    if (tid == 0) {
        float mx = -1e30f, mn = 1e30f;
        for (int i = 0; i < 8; i++) { mx = fmaxf(mx, s_red[i]); mn = fminf(mn, s_red[8+i]); }
        s_mx = mx; s_mn = mn;
    }
    __syncthreads();
    float mn = s_mn, den = s_mx - s_mn + 1e-8f;
    for (int v = tid; v < NV; v += 256)
        out[O_GN + (size_t)idx*NV + v] = (s_perm[v] - mn) / den;
}

// ---------------- top-view slice + rot + global reduce ----------------
__global__ void k_top(const float* __restrict__ gl, const float* __restrict__ gw,
                      float* __restrict__ out)
{
    __shared__ float s_top[48];
    int idx = blockIdx.x;
    int b = idx / NSd;
    int tid = threadIdx.x;
    int nn = g_nn[idx];
    int tv = g_topv[idx];
    int ut = g_view_inds[b*NV + tv];
    const float* rs = gl + (size_t)(b*NGd + nn)*(NV*48) + ut*48;
    const float* rw = gw + (size_t)(b*NGd + nn)*(NV*48) + ut*48;
    if (tid < 48) {
        float sc = __ldg(rs + tid);
        float wd = __ldg(rw + tid);
        bool lm = (sc > 0.f) & (wd <= 0.1f);
        float scv = lm ? sc : 0.f;
        out[O_TSC + (size_t)idx*48 + tid] = scv;
        out[O_TWD + (size_t)idx*48 + tid] = wd;
        s_top[tid] = scv;
    } else if (tid < 57) {
        out[O_TROT + (size_t)idx*9 + (tid - 48)] = g_gvrot[(size_t)(b*NV + tv)*9 + (tid - 48)];
    }
    __syncthreads();
    if (tid == 0) {
        float mx = 0.f, mnp = 1e30f; bool any = false;
        for (int i = 0; i < 48; i++) {
            float v = s_top[i];
            mx = fmaxf(mx, v);
            if (v > 0.f) { any = true; mnp = fminf(mnp, v); }
        }
        atomicMax(&g_umax, __float_as_uint(mx));
        if (any) atomicMin(&g_umin, __float_as_uint(mnp));
    }
}

__global__ void k_finalize(float* __restrict__ out)
{
    int i = blockIdx.x*blockDim.x + threadIdx.x;
    if (i >= BB*NSd*48) return;
    float v = out[O_TSC + i];
    if (v > 0.f) {
        float umax = __uint_as_float(g_umax);
        float umin = __uint_as_float(g_umin);
        out[O_TSC + i] = logf(umax / v) / (logf(umax / umin) + 1e-8f);
    }
}

// ---------------------------------------------------------------
extern "C" void kernel_launch(void* const* d_in, const int* in_sizes, int n_in,
                              void* d_out, int out_size)
{
    const float* seed  = (const float*)d_in[0];
    const float* pc    = (const float*)d_in[1];
    const float* pose  = (const float*)d_in[2];
    const float* gpts  = (const float*)d_in[3];
    const float* gl    = (const float*)d_in[4];
    const float* gw    = (const float*)d_in[5];
    const float* aw1w  = (const float*)d_in[6];
    const float* aw1b  = (const float*)d_in[7];
    const float* aw2w  = (const float*)d_in[8];
    const float* aw2b  = (const float*)d_in[9];
    const float* aw3w  = (const float*)d_in[10];
    const float* aw3b  = (const float*)d_in[11];
    const float* sw1w  = (const float*)d_in[12];
    const float* sw1b  = (const float*)d_in[13];
    const float* sw2w  = (const float*)d_in[14];
    const float* sw2b  = (const float*)d_in[15];
    float* out = (float*)d_out;

    static bool s_init = false;
    static cudaStream_t sA, sB;
    static cudaEvent_t e0, e1, eA, eB;
    static float *p_tmp = nullptr, *p_res = nullptr;
    if (!s_init) {
        cudaStreamCreateWithFlags(&sA, cudaStreamNonBlocking);
        cudaStreamCreateWithFlags(&sB, cudaStreamNonBlocking);
        cudaEventCreateWithFlags(&e0, cudaEventDisableTiming);
        cudaEventCreateWithFlags(&e1, cudaEventDisableTiming);
        cudaEventCreateWithFlags(&eA, cudaEventDisableTiming);
        cudaEventCreateWithFlags(&eB, cudaEventDisableTiming);
        cudaGetSymbolAddress((void**)&p_tmp, g_tmp);
        cudaGetSymbolAddress((void**)&p_res, g_res);
        s_init = true;
    }

    // main stream: tiny setup
    k_init_reduce<<<1, 1>>>();
    k_views<<<1, 320>>>();
    k_batch<<<BB, 320>>>(pose);
    cudaEventRecord(e0, 0);

    // stream A: DRAM-heavy pipeline, overlapped with GEMM chain
    cudaStreamWaitEvent(sA, e0, 0);
    k_gptrans<<<(BB*NGd + 255)/256, 256, 0, sA>>>(gpts);
    k_nn<<<dim3(NSd/256, BB), 256, 0, sA>>>(pc, out);
    k_count<<<BB*NSd, 256, 0, sA>>>(gl, out);
    cudaEventRecord(eA, sA);

    // main stream: GEMM chain
    k_gemm<128,128,8,8,0,1,false><<<dim3(16,4,BB), 256>>>(aw1w, seed,  aw1b, p_tmp, 512);
    k_gemm<128,128,8,8,0,1,false><<<dim3(16,4,BB), 256>>>(aw2w, p_tmp, aw2b, p_res, 512);
    cudaEventRecord(e1, 0);

    // stream B: sw branch (only needs g_res)
    cudaStreamWaitEvent(sB, e1, 0);
    k_gemm<128,128,8,8,0,1,false><<<dim3(16,4,BB), 256, 0, sB>>>(sw1w, p_res, sw1b, p_tmp, 512);
    k_gemm<32,128,2,8,2,0,false><<<dim3(16,3,BB), 256, 0, sB>>>(sw2w, p_tmp, sw2b, out, 96);
    cudaEventRecord(eB, sB);

    // main stream: view-score branch
    k_gemm<64,128,4,8,1,0,true><<<dim3(16,5,BB), 256>>>(aw3w, p_res, aw3b, out, 300);
    k_argmax<<<(BB*NSd*32)/256, 256>>>(out);

    // join and finish
    cudaStreamWaitEvent((cudaStream_t)0, eA, 0);
    cudaStreamWaitEvent((cudaStream_t)0, eB, 0);
    k_top<<<BB*NSd, 64>>>(gl, gw, out);
    k_finalize<<<(BB*NSd*48 + 255)/256, 256>>>(out);
}

// round 8
// speedup vs baseline: 1.0869x; 1.0162x over previous
#include <cuda_runtime.h>

#define BB 2
#define CC 512
#define NSd 2048
#define NGd 2000
#define NV 300

typedef unsigned long long ull;

#define FMA2(d,a,b,c) asm("fma.rn.f32x2 %0, %1, %2, %3;" : "=l"(d) : "l"(a), "l"(b), "l"(c))

// ---- output layout (floats), concatenated reference tuple ----
static constexpr size_t O_VS    = 0;                                   // (B,NS,300)
static constexpr size_t O_VPROT = O_VS    + (size_t)BB*NSd*NV;         // (B,NS,3,3)
static constexpr size_t O_SC    = O_VPROT + (size_t)BB*NSd*9;          // (B,NS,12,4)
static constexpr size_t O_WD    = O_SC    + (size_t)BB*NSd*48;         // (B,NS,12,4)
static constexpr size_t O_TROT  = O_WD    + (size_t)BB*NSd*48;         // (B,NS,3,3)
static constexpr size_t O_TSC   = O_TROT  + (size_t)BB*NSd*9;          // (B,NS,12,4)
static constexpr size_t O_TWD   = O_TSC   + (size_t)BB*NSd*48;         // (B,NS,12,4)
static constexpr size_t O_GN    = O_TWD   + (size_t)BB*NSd*48;         // (B,NS,300)
static constexpr size_t O_GP    = O_GN    + (size_t)BB*NSd*NV;         // (B,NS,3)

// ---- device scratch (no allocations allowed) ----
__device__ float g_views[NV*3];
__device__ float g_views_rot[NV*9];
__device__ float g_R[BB*9];
__device__ float g_t[BB*3];
__device__ int   g_view_inds[BB*NV];
__device__ float g_gvrot[BB*NV*9];
__device__ float g_gpt[BB*NGd*3];
__device__ int   g_nn[BB*NSd];
__device__ int   g_topv[BB*NSd];
__device__ float g_tmp[(size_t)BB*CC*NSd];
__device__ float g_res[(size_t)BB*CC*NSd];
__device__ unsigned g_umax, g_umin;

// ---------------------------------------------------------------
__device__ __forceinline__ void make_rot(float tx_, float ty_, float tz_, float* m)
{
    float ax0 = tx_, ax1 = ty_, ax2 = tz_;
    float ay0 = -ax1, ay1 = ax0, ay2 = 0.f;
    float yn = sqrtf(ay0*ay0 + ay1*ay1 + ay2*ay2);
    if (yn == 0.f) { ay0 = 0.f; ay1 = 1.f; ay2 = 0.f; }
    float an = sqrtf(ax0*ax0 + ax1*ax1 + ax2*ax2);
    ax0 /= an; ax1 /= an; ax2 /= an;
    float an2 = sqrtf(ay0*ay0 + ay1*ay1 + ay2*ay2);
    ay0 /= an2; ay1 /= an2; ay2 /= an2;
    float az0 = ax1*ay2 - ax2*ay1;
    float az1 = ax2*ay0 - ax0*ay2;
    float az2 = ax0*ay1 - ax1*ay0;
    m[0]=ax0; m[1]=ay0; m[2]=az0;
    m[3]=ax1; m[4]=ay1; m[5]=az1;
    m[6]=ax2; m[7]=ay2; m[8]=az2;
}

__global__ void k_views()
{
    int v = threadIdx.x;
    if (v >= NV) return;
    float fv = (float)v;
    float Z = (2.f*fv + 1.f) / 300.f - 1.f;
    float r = sqrtf(fmaxf(1.f - Z*Z, 0.f));
    float ang = (6.2831853071795864769f * fv) * 0.61803398874989484820f;
    float X = r * cosf(ang);
    float Y = r * sinf(ang);
    g_views[v*3+0] = X; g_views[v*3+1] = Y; g_views[v*3+2] = Z;
    make_rot(-X, -Y, -Z, &g_views_rot[v*9]);
}

__global__ void k_batch(const float* __restrict__ pose)
{
    __shared__ float sR[9];
    __shared__ float sgx[NV], sgy[NV], sgz[NV], srr[NV];
    int b = blockIdx.x, tid = threadIdx.x;
    if (tid < 9) {
        float val = pose[b*12 + (tid/3)*4 + (tid%3)];
        sR[tid] = val; g_R[b*9+tid] = val;
    }
    if (tid < 3) g_t[b*3+tid] = pose[b*12 + tid*4 + 3];
    __syncthreads();
    if (tid < NV) {
        float vx = g_views[tid*3], vy = g_views[tid*3+1], vz = g_views[tid*3+2];
        float gx = sR[0]*vx + sR[1]*vy + sR[2]*vz;
        float gy = sR[3]*vx + sR[4]*vy + sR[5]*vz;
        float gz = sR[6]*vx + sR[7]*vy + sR[8]*vz;
        sgx[tid]=gx; sgy[tid]=gy; sgz[tid]=gz;
        srr[tid]=gx*gx + gy*gy + gz*gz;
    }
    __syncthreads();
    if (tid < NV) {
        float qx = g_views[tid*3], qy = g_views[tid*3+1], qz = g_views[tid*3+2];
        float qq = qx*qx + qy*qy + qz*qz;
        float best = 1e30f; int bi = 0;
        for (int u = 0; u < NV; u++) {
            float d = (qq + srr[u]) - 2.f*(qx*sgx[u] + qy*sgy[u] + qz*sgz[u]);
            if (d < best) { best = d; bi = u; }
        }
        g_view_inds[b*NV + tid] = bi;
        const float* VR = g_views_rot + bi*9;
        float* O = g_gvrot + (size_t)(b*NV + tid)*9;
#pragma unroll
        for (int i = 0; i < 3; i++)
#pragma unroll
            for (int j = 0; j < 3; j++)
                O[i*3+j] = sR[i*3+0]*VR[0+j] + sR[i*3+1]*VR[3+j] + sR[i*3+2]*VR[6+j];
    }
}

__global__ void k_gptrans(const float* __restrict__ gp)
{
    int idx = blockIdx.x*blockDim.x + threadIdx.x;
    if (idx >= BB*NGd) return;
    int b = idx / NGd;
    float p0 = gp[idx*3+0], p1 = gp[idx*3+1], p2 = gp[idx*3+2];
    const float* R = g_R + b*9;
    const float* t = g_t + b*3;
    g_gpt[idx*3+0] = R[0]*p0 + R[1]*p1 + R[2]*p2 + t[0];
    g_gpt[idx*3+1] = R[3]*p0 + R[4]*p1 + R[5]*p2 + t[1];
    g_gpt[idx*3+2] = R[6]*p0 + R[7]*p1 + R[8]*p2 + t[2];
}

// ---------------- FFMA2 SGEMM: Y = act(W @ X + b) ----------------
// TN=8 fixed, split as two 4-col groups (tx*4 and BN/2+tx*4) -> conflict-free
// LDS.128. A stored duplicated in smem so (a,a) pairs come from LDS.128.
template<int BM,int BN,int TM,int MODE,int RELU,bool GUARD>
__global__ __launch_bounds__(256) void k_gemm(
    const float* __restrict__ W, const float* __restrict__ X,
    const float* __restrict__ bias, float* __restrict__ Y, int M)
{
    constexpr int K = CC, N = NSd, BKc = 8, TN = 8;
    constexpr int NXt = BN/TN;            // 16
    constexpr int AELT = BM*BKc/256;
    constexpr int BELT = BN*BKc/256;
    constexpr int AW = 2*BM + 4;          // keeps rows 16B-aligned
    __shared__ float As[2][BKc][AW];
    __shared__ float Bs[2][BKc][BN];
    const int b   = blockIdx.z;
    const int bm0 = blockIdx.y * BM;
    const int bn0 = blockIdx.x * BN;
    const float* Xb = X + (size_t)b*K*N + bn0;
    const float* Wb = W + (size_t)bm0*K;
    const int tid = threadIdx.x;
    const int tx = tid % NXt, ty = tid / NXt;

    ull acc2[TM][4];
#pragma unroll
    for (int i=0;i<TM;i++)
#pragma unroll
        for (int j=0;j<4;j++) acc2[i][j] = 0ull;
    float areg[AELT], breg[BELT];

    // chunk 0
#pragma unroll
    for (int e=0;e<AELT;e++){
        int i = tid + e*256;
        int m = i/BKc, kk = i%BKc;
        float v = 0.f;
        if (!GUARD || (bm0+m) < M) v = Wb[(size_t)m*K + kk];
        *(float2*)&As[0][kk][2*m] = make_float2(v, v);
    }
#pragma unroll
    for (int e=0;e<BELT;e++){
        int i = tid + e*256;
        int kk = i/BN, n = i%BN;
        Bs[0][kk][n] = Xb[(size_t)kk*N + n];
    }
    __syncthreads();

    for (int ck=0; ck<K/BKc; ck++){
        const int buf = ck & 1;
        if (ck+1 < K/BKc){
            int k0 = (ck+1)*BKc;
#pragma unroll
            for (int e=0;e<AELT;e++){
                int i = tid + e*256;
                int m = i/BKc, kk = i%BKc;
                float v = 0.f;
                if (!GUARD || (bm0+m) < M) v = Wb[(size_t)m*K + k0 + kk];
                areg[e] = v;
            }
#pragma unroll
            for (int e=0;e<BELT;e++){
                int i = tid + e*256;
                int kk = i/BN, n = i%BN;
                breg[e] = Xb[(size_t)(k0+kk)*N + n];
            }
        }
#pragma unroll
        for (int kk=0;kk<BKc;kk++){
            ull af2[TM];
#pragma unroll
            for (int i2=0;i2<TM/2;i2++){
                ulonglong2 av = *(const ulonglong2*)&As[buf][kk][ty*TM*2 + i2*4];
                af2[2*i2]   = av.x;
                af2[2*i2+1] = av.y;
            }
            ulonglong2 b0 = *(const ulonglong2*)&Bs[buf][kk][tx*4];
            ulonglong2 b1 = *(const ulonglong2*)&Bs[buf][kk][BN/2 + tx*4];
            ull bf2[4] = {b0.x, b0.y, b1.x, b1.y};
#pragma unroll
            for (int i=0;i<TM;i++)
#pragma unroll
                for (int j=0;j<4;j++)
                    FMA2(acc2[i][j], af2[i], bf2[j], acc2[i][j]);
        }
        if (ck+1 < K/BKc){
            const int nb = buf^1;
#pragma unroll
            for (int e=0;e<AELT;e++){
                int i = tid + e*256;
                *(float2*)&As[nb][i%BKc][2*(i/BKc)] = make_float2(areg[e], areg[e]);
            }
#pragma unroll
            for (int e=0;e<BELT;e++){ int i = tid + e*256; Bs[nb][i/BN][i%BN] = breg[e]; }
        }
        __syncthreads();
    }

#pragma unroll
    for (int i=0;i<TM;i++){
        int m = bm0 + ty*TM + i;
        if (GUARD && m >= M) continue;
        float bv = bias[m];
        float c[8];
#pragma unroll
        for (int j=0;j<4;j++){
            c[2*j]   = __uint_as_float((unsigned)(acc2[i][j] & 0xffffffffull)) + bv;
            c[2*j+1] = __uint_as_float((unsigned)(acc2[i][j] >> 32)) + bv;
        }
        if (RELU){
#pragma unroll
            for (int j=0;j<8;j++) c[j] = fmaxf(c[j], 0.f);
        }
        if (MODE == 0) {
            *(float4*)&Y[((size_t)b*M + m)*N + bn0 + tx*4]          = make_float4(c[0],c[1],c[2],c[3]);
            *(float4*)&Y[((size_t)b*M + m)*N + bn0 + BN/2 + tx*4]   = make_float4(c[4],c[5],c[6],c[7]);
        } else {
#pragma unroll
            for (int g=0; g<2; g++){
#pragma unroll
                for (int jj=0;jj<4;jj++){
                    int n = bn0 + g*(BN/2) + tx*4 + jj;
                    float v = c[g*4 + jj];
                    if (MODE == 1) {
                        Y[O_VS + ((size_t)b*N + n)*NV + m] = v;
                    } else {
                        size_t base = (m < 48)
                            ? O_SC + ((size_t)b*NSd + n)*48 + m
                            : O_WD + ((size_t)b*NSd + n)*48 + (m - 48);
                        Y[base] = v;
                    }
                }
            }
        }
    }
}

// ---------------- argmax over views + vp_rot ----------------
__global__ void k_argmax(float* __restrict__ out)
{
    int g = (blockIdx.x * blockDim.x + threadIdx.x) >> 5;
    int lane = threadIdx.x & 31;
    if (g >= BB*NSd) return;
    const float* vs = out + O_VS + (size_t)g * NV;
    float best = -1e30f; int bi = 1 << 30;
    for (int v = lane; v < NV; v += 32) {
        float val = vs[v];
        if (val > best) { best = val; bi = v; }
    }
#pragma unroll
    for (int off = 16; off; off >>= 1) {
        float ob = __shfl_xor_sync(0xffffffffu, best, off);
        int   oi = __shfl_xor_sync(0xffffffffu, bi,  off);
        if (ob > best || (ob == best && oi < bi)) { best = ob; bi = oi; }
    }
    if (lane == 0) {
        g_topv[g] = bi;
        float m[9];
        make_rot(-g_views[bi*3], -g_views[bi*3+1], -g_views[bi*3+2], m);
        float* o = out + O_VPROT + (size_t)g*9;
#pragma unroll
        for (int i = 0; i < 9; i++) o[i] = m[i];
    }
}

// ---------------- kNN seeds -> grasp points, gp gather ----------------
__global__ void k_nn(const float* __restrict__ pc, float* __restrict__ out)
{
    __shared__ float sx[256], sy[256], sz[256], sr[256];
    int b = blockIdx.y;
    int n = blockIdx.x*256 + threadIdx.x;
    float qx = pc[((size_t)b*NSd + n)*3 + 0];
    float qy = pc[((size_t)b*NSd + n)*3 + 1];
    float qz = pc[((size_t)b*NSd + n)*3 + 2];
    float qq = qx*qx + qy*qy + qz*qz;
    float best = 1e30f; int bi = 0;
    for (int t0 = 0; t0 < NGd; t0 += 256) {
        int r = t0 + threadIdx.x;
        if (r < NGd) {
            float x = g_gpt[((size_t)b*NGd + r)*3 + 0];
            float y = g_gpt[((size_t)b*NGd + r)*3 + 1];
            float z = g_gpt[((size_t)b*NGd + r)*3 + 2];
            sx[threadIdx.x] = x; sy[threadIdx.x] = y; sz[threadIdx.x] = z;
            sr[threadIdx.x] = x*x + y*y + z*z;
        } else { sx[threadIdx.x] = 0.f; sy[threadIdx.x] = 0.f; sz[threadIdx.x] = 0.f; sr[threadIdx.x] = 1e30f; }
        __syncthreads();
        int cnt = min(256, NGd - t0);
        for (int j = 0; j < cnt; j++) {
            float d = (qq + sr[j]) - 2.f*(qx*sx[j] + qy*sy[j] + qz*sz[j]);
            if (d < best) { best = d; bi = t0 + j; }
        }
        __syncthreads();
    }
    g_nn[b*NSd + n] = bi;
    out[O_GP + ((size_t)b*NSd + n)*3 + 0] = g_gpt[((size_t)b*NGd + bi)*3 + 0];
    out[O_GP + ((size_t)b*NSd + n)*3 + 1] = g_gpt[((size_t)b*NGd + bi)*3 + 1];
    out[O_GP + ((size_t)b*NSd + n)*3 + 2] = g_gpt[((size_t)b*NGd + bi)*3 + 2];
}

__global__ void k_init_reduce()
{
    g_umax = 0u;
    g_umin = 0x7f800000u;
}

// ---------------- graspness (heavy scan, overlapped with GEMMs) ----------------
__global__ __launch_bounds__(256) void k_count(
    const float* __restrict__ gl, float* __restrict__ out)
{
    __shared__ float s_cnt[NV];
    __shared__ int   s_vi[NV];
    __shared__ float s_perm[NV];
    __shared__ float s_red[16];
    __shared__ float s_mx, s_mn;

    int idx = blockIdx.x;              // b*NSd + n
    int b = idx / NSd;
    int tid = threadIdx.x;
    int lane = tid & 31, w = tid >> 5;

    int nn = g_nn[idx];
    for (int v = tid; v < NV; v += 256) s_vi[v] = g_view_inds[b*NV + v];

    const float* row = gl + (size_t)(b*NGd + nn) * (NV*48);
    for (int u = w; u < NV; u += 8) {
        const float* p = row + u*48;
        float v1 = __ldg(p + lane);
        bool m1 = (v1 > 0.f) & (v1 <= 0.6f);
        bool m2 = false;
        if (lane < 16) { float v2 = __ldg(p + 32 + lane); m2 = (v2 > 0.f) & (v2 <= 0.6f); }
        unsigned b1 = __ballot_sync(0xffffffffu, m1);
        unsigned b2 = __ballot_sync(0xffffffffu, m2);
        if (lane == 0) s_cnt[u] = (float)(__popc(b1) + __popc(b2));
    }
    __syncthreads();

    float lmx = -1e30f, lmn = 1e30f;
    for (int v = tid; v < NV; v += 256) {
        float gv = s_cnt[s_vi[v]] * (1.f/48.f);
        s_perm[v] = gv;
        lmx = fmaxf(lmx, gv); lmn = fminf(lmn, gv);
    }
#pragma unroll
    for (int off = 16; off; off >>= 1) {
        lmx = fmaxf(lmx, __shfl_xor_sync(0xffffffffu, lmx, off));
        lmn = fminf(lmn, __shfl_xor_sync(0xffffffffu, lmn, off));
    }
    if (lane == 0) { s_red[w] = lmx; s_red[8+w] = lmn; }
    __syncthreads();
    if (tid == 0) {
        float mx = -1e30f, mn = 1e30f;
        for (int i = 0; i < 8; i++) { mx = fmaxf(mx, s_red[i]); mn = fminf(mn, s_red[8+i]); }
        s_mx = mx; s_mn = mn;
    }
    __syncthreads();
    float mn = s_mn, den = s_mx - s_mn + 1e-8f;
    for (int v = tid; v < NV; v += 256)
        out[O_GN + (size_t)idx*NV + v] = (s_perm[v] - mn) / den;
}

// ---------------- top-view slice + rot + global reduce ----------------
__global__ void k_top(const float* __restrict__ gl, const float* __restrict__ gw,
                      float* __restrict__ out)
{
    __shared__ float s_top[48];
    int idx = blockIdx.x;
    int b = idx / NSd;
    int tid = threadIdx.x;
    int nn = g_nn[idx];
    int tv = g_topv[idx];
    int ut = g_view_inds[b*NV + tv];
    const float* rs = gl + (size_t)(b*NGd + nn)*(NV*48) + ut*48;
    const float* rw = gw + (size_t)(b*NGd + nn)*(NV*48) + ut*48;
    if (tid < 48) {
        float sc = __ldg(rs + tid);
        float wd = __ldg(rw + tid);
        bool lm = (sc > 0.f) & (wd <= 0.1f);
        float scv = lm ? sc : 0.f;
        out[O_TSC + (size_t)idx*48 + tid] = scv;
        out[O_TWD + (size_t)idx*48 + tid] = wd;
        s_top[tid] = scv;
    } else if (tid < 57) {
        out[O_TROT + (size_t)idx*9 + (tid - 48)] = g_gvrot[(size_t)(b*NV + tv)*9 + (tid - 48)];
    }
    __syncthreads();
    if (tid == 0) {
        float mx = 0.f, mnp = 1e30f; bool any = false;
        for (int i = 0; i < 48; i++) {
            float v = s_top[i];
            mx = fmaxf(mx, v);
            if (v > 0.f) { any = true; mnp = fminf(mnp, v); }
        }
        atomicMax(&g_umax, __float_as_uint(mx));
        if (any) atomicMin(&g_umin, __float_as_uint(mnp));
    }
}

__global__ void k_finalize(float* __restrict__ out)
{
    int i = blockIdx.x*blockDim.x + threadIdx.x;
    if (i >= BB*NSd*48) return;
    float v = out[O_TSC + i];
    if (v > 0.f) {
        float umax = __uint_as_float(g_umax);
        float umin = __uint_as_float(g_umin);
        out[O_TSC + i] = logf(umax / v) / (logf(umax / umin) + 1e-8f);
    }
}

// ---------------------------------------------------------------
extern "C" void kernel_launch(void* const* d_in, const int* in_sizes, int n_in,
                              void* d_out, int out_size)
{
    const float* seed  = (const float*)d_in[0];
    const float* pc    = (const float*)d_in[1];
    const float* pose  = (const float*)d_in[2];
    const float* gpts  = (const float*)d_in[3];
    const float* gl    = (const float*)d_in[4];
    const float* gw    = (const float*)d_in[5];
    const float* aw1w  = (const float*)d_in[6];
    const float* aw1b  = (const float*)d_in[7];
    const float* aw2w  = (const float*)d_in[8];
    const float* aw2b  = (const float*)d_in[9];
    const float* aw3w  = (const float*)d_in[10];
    const float* aw3b  = (const float*)d_in[11];
    const float* sw1w  = (const float*)d_in[12];
    const float* sw1b  = (const float*)d_in[13];
    const float* sw2w  = (const float*)d_in[14];
    const float* sw2b  = (const float*)d_in[15];
    float* out = (float*)d_out;

    static bool s_init = false;
    static cudaStream_t sA, sB;
    static cudaEvent_t e0, e1, eA, eB;
    static float *p_tmp = nullptr, *p_res = nullptr;
    if (!s_init) {
        cudaStreamCreateWithFlags(&sA, cudaStreamNonBlocking);
        cudaStreamCreateWithFlags(&sB, cudaStreamNonBlocking);
        cudaEventCreateWithFlags(&e0, cudaEventDisableTiming);
        cudaEventCreateWithFlags(&e1, cudaEventDisableTiming);
        cudaEventCreateWithFlags(&eA, cudaEventDisableTiming);
        cudaEventCreateWithFlags(&eB, cudaEventDisableTiming);
        cudaGetSymbolAddress((void**)&p_tmp, g_tmp);
        cudaGetSymbolAddress((void**)&p_res, g_res);
        s_init = true;
    }

    // main stream: tiny setup
    k_init_reduce<<<1, 1>>>();
    k_views<<<1, 320>>>();
    k_batch<<<BB, 320>>>(pose);
    cudaEventRecord(e0, 0);

    // stream A: DRAM-heavy pipeline, overlapped with GEMM chain
    cudaStreamWaitEvent(sA, e0, 0);
    k_gptrans<<<(BB*NGd + 255)/256, 256, 0, sA>>>(gpts);
    k_nn<<<dim3(NSd/256, BB), 256, 0, sA>>>(pc, out);
    k_count<<<BB*NSd, 256, 0, sA>>>(gl, out);
    cudaEventRecord(eA, sA);

    // main stream: GEMM chain (FFMA2)
    k_gemm<128,128,8,0,1,false><<<dim3(16,4,BB), 256>>>(aw1w, seed,  aw1b, p_tmp, 512);
    k_gemm<128,128,8,0,1,false><<<dim3(16,4,BB), 256>>>(aw2w, p_tmp, aw2b, p_res, 512);
    cudaEventRecord(e1, 0);

    // stream B: sw branch (only needs g_res)
    cudaStreamWaitEvent(sB, e1, 0);
    k_gemm<128,128,8,0,1,false><<<dim3(16,4,BB), 256, 0, sB>>>(sw1w, p_res, sw1b, p_tmp, 512);
    k_gemm<32,128,2,2,0,false><<<dim3(16,3,BB), 256, 0, sB>>>(sw2w, p_tmp, sw2b, out, 96);
    cudaEventRecord(eB, sB);

    // main stream: view-score branch
    k_gemm<64,128,4,1,0,true><<<dim3(16,5,BB), 256>>>(aw3w, p_res, aw3b, out, 300);
    k_argmax<<<(BB*NSd*32)/256, 256>>>(out);

    // join and finish
    cudaStreamWaitEvent((cudaStream_t)0, eA, 0);
    cudaStreamWaitEvent((cudaStream_t)0, eB, 0);
    k_top<<<BB*NSd, 64>>>(gl, gw, out);
    k_finalize<<<(BB*NSd*48 + 255)/256, 256>>>(out);
}